// round 4
// baseline (speedup 1.0000x reference)
#include <cuda_runtime.h>
#include <math.h>

// ---------------------------------------------------------------------------
// ZBLRepulsion: per-edge repulsion energy + segment_sum over receivers.
//   N_NODES = 1,000,000   N_EDGES = 32,000,000   N_SPECIES = 100
//
// Bottleneck (measured R3): l1tex wavefronts from 64M random byte gathers +
// 32M spread REDG = ~96M wf ~= 650K cyc/SM ~= 345us. This round: margin
// recovery (4 edges/thread, one-exp switching fn, max-L1 carveout).
// ---------------------------------------------------------------------------

#define KE_CONST 14.399645351950548
#define MAX_NODES   1000000
#define MAX_SPECIES 128

__device__ float  g_params[8];                      // a0..a3, c0..3 (*KE/2)
__device__ float2 g_stab[MAX_SPECIES];              // per-species {z, d*z^p}
__device__ uchar4 g_spec4[(MAX_NODES + 3) / 4];     // packed species bytes

__device__ __forceinline__ float softplus_f(float x) {
    return fmaxf(x, 0.0f) + log1pf(expf(-fabsf(x)));
}

// ---- kernel 0: fused prep -------------------------------------------------
__global__ void zbl_prep_kernel(const float* __restrict__ a_raw,
                                const float* __restrict__ c_raw,
                                const float* __restrict__ p_raw,
                                const float* __restrict__ d_raw,
                                const int* __restrict__ index_to_z,
                                const int* __restrict__ species,
                                float* __restrict__ out,
                                int n_species, int n_nodes, int out_n) {
    if (blockIdx.x == 0) {
        int t = threadIdx.x;
        if (t < n_species) {
            float p  = softplus_f(p_raw[0]);
            float d  = softplus_f(d_raw[0]);
            float zf = (float)index_to_z[t];
            g_stab[t] = make_float2(zf, d * powf(zf, p));
        }
        if (t == 0) {
            float c[4], csum = 0.0f;
#pragma unroll
            for (int k = 0; k < 4; k++) {
                g_params[k] = softplus_f(a_raw[k]);
                c[k] = softplus_f(c_raw[k]);
                csum += c[k];
            }
            float scale = (float)(KE_CONST * 0.5) / csum;
#pragma unroll
            for (int k = 0; k < 4; k++) g_params[4 + k] = c[k] * scale;
        }
    }

    int q = blockIdx.x * blockDim.x + threadIdx.x;
    int base = q * 4;
    if (base + 3 < n_nodes) {
        int4 s = *reinterpret_cast<const int4*>(species + base);
        g_spec4[q] = make_uchar4((unsigned char)s.x, (unsigned char)s.y,
                                 (unsigned char)s.z, (unsigned char)s.w);
    } else if (base < n_nodes) {
        unsigned char* sp = reinterpret_cast<unsigned char*>(g_spec4);
        for (int k = base; k < n_nodes; k++) sp[k] = (unsigned char)species[k];
    }
    if (base + 3 < out_n) {
        *reinterpret_cast<float4*>(out + base) = make_float4(0.f, 0.f, 0.f, 0.f);
    } else if (base < out_n) {
        for (int k = base; k < out_n; k++) out[k] = 0.0f;
    }
}

// ---- per-edge math --------------------------------------------------------
__device__ __forceinline__ float zbl_energy(float dd, float ct,
                                            unsigned int si, unsigned int ri,
                                            const float* __restrict__ P,
                                            const float2* __restrict__ stab) {
    float2 nj = stab[si];
    float2 ni = stab[ri];

    float x   = ct * ni.x * nj.x * __fdividef(1.0f, dd + 1e-8f);
    float rzd = dd * (ni.y + nj.y);

    float y = P[4] * __expf(-P[0] * rzd)
            + P[5] * __expf(-P[1] * rzd)
            + P[6] * __expf(-P[2] * rzd)
            + P[7] * __expf(-P[3] * rzd);

    // w = e2/(e1+e2) = 1/(1 + exp(1/t2 - 1/t1))   (one exp instead of two)
    float sd = dd * (1.0f / 1.5f);
    float g  = __fdividef(1.0f, fmaxf(1.0f - sd, 1e-8f))
             - __fdividef(1.0f, fmaxf(sd,        1e-8f));
    float w  = __frcp_rn(1.0f + __expf(g));

    return w * x * y;
}

// ---- kernel 1: edge loop, 4 edges/thread ----------------------------------
__global__ void __launch_bounds__(256)
zbl_edge_kernel(const float* __restrict__ distances,
                const float* __restrict__ cutoffs,
                const int* __restrict__ senders,
                const int* __restrict__ receivers,
                float* __restrict__ out,
                int n_edges, int n_species) {
    __shared__ float2 stab[MAX_SPECIES];
    for (int t = threadIdx.x; t < n_species; t += blockDim.x)
        stab[t] = g_stab[t];
    float P[8];
#pragma unroll
    for (int k = 0; k < 8; k++) P[k] = g_params[k];
    __syncthreads();

    const unsigned char* spec = reinterpret_cast<const unsigned char*>(g_spec4);

    int i  = blockIdx.x * blockDim.x + threadIdx.x;
    long long e0 = (long long)i * 4;
    if (e0 >= n_edges) return;

    if (e0 + 3 < n_edges) {
        float4 d4 = __ldcs(reinterpret_cast<const float4*>(distances + e0));
        float4 c4 = __ldcs(reinterpret_cast<const float4*>(cutoffs   + e0));
        int4   s4 = __ldcs(reinterpret_cast<const int4*>(senders    + e0));
        int4   r4 = __ldcs(reinterpret_cast<const int4*>(receivers  + e0));

        // all 8 gathers in flight before compute
        unsigned int sa = __ldg(spec + s4.x), ra = __ldg(spec + r4.x);
        unsigned int sb = __ldg(spec + s4.y), rb = __ldg(spec + r4.y);
        unsigned int sc = __ldg(spec + s4.z), rc = __ldg(spec + r4.z);
        unsigned int sd_ = __ldg(spec + s4.w), rd = __ldg(spec + r4.w);

        float va = zbl_energy(d4.x, c4.x, sa, ra, P, stab);
        float vb = zbl_energy(d4.y, c4.y, sb, rb, P, stab);
        float vc = zbl_energy(d4.z, c4.z, sc, rc, P, stab);
        float vd = zbl_energy(d4.w, c4.w, sd_, rd, P, stab);

        atomicAdd(out + r4.x, va);
        atomicAdd(out + r4.y, vb);
        atomicAdd(out + r4.z, vc);
        atomicAdd(out + r4.w, vd);
    } else {
        for (long long e = e0; e < n_edges; e++) {
            unsigned int si = spec[senders[e]];
            unsigned int ri = spec[receivers[e]];
            float v = zbl_energy(distances[e], cutoffs[e], si, ri, P, stab);
            atomicAdd(out + receivers[e], v);
        }
    }
}

// ---------------------------------------------------------------------------
extern "C" void kernel_launch(void* const* d_in, const int* in_sizes, int n_in,
                              void* d_out, int out_size) {
    const int*   node_species = (const int*)  d_in[0];
    const float* distances    = (const float*)d_in[1];
    const float* cutoffs      = (const float*)d_in[2];
    const int*   senders      = (const int*)  d_in[3];
    const int*   receivers    = (const int*)  d_in[4];
    const int*   index_to_z   = (const int*)  d_in[5];
    const float* a_raw        = (const float*)d_in[6];
    const float* c_raw        = (const float*)d_in[7];
    const float* p_raw        = (const float*)d_in[8];
    const float* d_raw        = (const float*)d_in[9];

    int n_nodes   = in_sizes[0];
    int n_edges   = in_sizes[1];
    int n_species = in_sizes[5];
    float* out    = (float*)d_out;

    // prefer max L1 (species-gather hit rate); smem use is ~1KB
    static int carveout_set = 0;
    if (!carveout_set) {
        cudaFuncSetAttribute(zbl_edge_kernel,
                             cudaFuncAttributePreferredSharedMemoryCarveout, 0);
        carveout_set = 1;
    }

    {
        int n = (n_nodes > out_size) ? n_nodes : out_size;
        int quads   = (n + 3) / 4;
        int threads = 256;
        int blocks  = (quads + threads - 1) / threads;
        zbl_prep_kernel<<<blocks, threads>>>(a_raw, c_raw, p_raw, d_raw,
                                             index_to_z, node_species, out,
                                             n_species, n_nodes, out_size);
    }

    {
        int threads = 256;
        long long quads = ((long long)n_edges + 3) / 4;
        int blocks  = (int)((quads + threads - 1) / threads);
        zbl_edge_kernel<<<blocks, threads>>>(distances, cutoffs, senders,
                                             receivers, out, n_edges,
                                             n_species);
    }
}

// round 5
// speedup vs baseline: 1.0709x; 1.0709x over previous
#include <cuda_runtime.h>
#include <math.h>

// ---------------------------------------------------------------------------
// ZBLRepulsion: per-edge repulsion energy + segment_sum over receivers.
//   N_NODES = 1,000,000   N_EDGES = 32,000,000   N_SPECIES = 100
//
// Floor model (validated R3/R4): ~100M l1tex wavefronts (64M random species
// gathers + 32M spread RED + 4M streaming) ~= 355us; overlap at high
// occupancy buys ~25us. R4's smem-carveout attribute crushed occupancy
// (69%->46%) and cost 20us -> reverted. This round: exact R2 edge kernel
// (proven 338.6us total) + fused 2-launch prep.
// ---------------------------------------------------------------------------

#define KE_CONST 14.399645351950548
#define MAX_NODES   1000000
#define MAX_SPECIES 128

__device__ float  g_params[8];                      // a0..a3, c0..3 (*KE/2)
__device__ float2 g_stab[MAX_SPECIES];              // per-species {z, d*z^p}
__device__ uchar4 g_spec4[(MAX_NODES + 3) / 4];     // packed species bytes

__device__ __forceinline__ float softplus_f(float x) {
    return fmaxf(x, 0.0f) + log1pf(expf(-fabsf(x)));
}

// ---- kernel 0: fused prep (params+table in block 0; pack+zero everywhere) --
__global__ void zbl_prep_kernel(const float* __restrict__ a_raw,
                                const float* __restrict__ c_raw,
                                const float* __restrict__ p_raw,
                                const float* __restrict__ d_raw,
                                const int* __restrict__ index_to_z,
                                const int* __restrict__ species,
                                float* __restrict__ out,
                                int n_species, int n_nodes, int out_n) {
    if (blockIdx.x == 0) {
        int t = threadIdx.x;
        if (t < n_species) {
            float p  = softplus_f(p_raw[0]);
            float d  = softplus_f(d_raw[0]);
            float zf = (float)index_to_z[t];
            g_stab[t] = make_float2(zf, d * powf(zf, p));
        }
        if (t == 0) {
            float c[4], csum = 0.0f;
#pragma unroll
            for (int k = 0; k < 4; k++) {
                g_params[k] = softplus_f(a_raw[k]);
                c[k] = softplus_f(c_raw[k]);
                csum += c[k];
            }
            float scale = (float)(KE_CONST * 0.5) / csum;
#pragma unroll
            for (int k = 0; k < 4; k++) g_params[4 + k] = c[k] * scale;
        }
    }

    int q = blockIdx.x * blockDim.x + threadIdx.x;
    int base = q * 4;
    if (base + 3 < n_nodes) {
        int4 s = *reinterpret_cast<const int4*>(species + base);
        g_spec4[q] = make_uchar4((unsigned char)s.x, (unsigned char)s.y,
                                 (unsigned char)s.z, (unsigned char)s.w);
    } else if (base < n_nodes) {
        unsigned char* sp = reinterpret_cast<unsigned char*>(g_spec4);
        for (int k = base; k < n_nodes; k++) sp[k] = (unsigned char)species[k];
    }
    if (base + 3 < out_n) {
        *reinterpret_cast<float4*>(out + base) = make_float4(0.f, 0.f, 0.f, 0.f);
    } else if (base < out_n) {
        for (int k = base; k < out_n; k++) out[k] = 0.0f;
    }
}

// ---- per-edge math (R2 body: two-exp switching, MUFU fast paths) ----------
__device__ __forceinline__ float zbl_energy(float dd, float ct,
                                            unsigned int si, unsigned int ri,
                                            const float* __restrict__ P,
                                            const float2* __restrict__ stab) {
    float2 nj = stab[si];
    float2 ni = stab[ri];

    float x   = ct * ni.x * nj.x * __fdividef(1.0f, dd + 1e-8f);
    float rzd = dd * (ni.y + nj.y);

    float y = P[4] * __expf(-P[0] * rzd)
            + P[5] * __expf(-P[1] * rzd)
            + P[6] * __expf(-P[2] * rzd)
            + P[7] * __expf(-P[3] * rzd);

    float sd = dd * (1.0f / 1.5f);
    float e1 = __expf(-__fdividef(1.0f, fmaxf(sd, 1e-8f)));
    float e2 = __expf(-__fdividef(1.0f, fmaxf(1.0f - sd, 1e-8f)));
    float w  = __fdividef(e2, e1 + e2);

    return w * x * y;
}

// ---- kernel 1: edge loop, 4 edges/thread (R2 configuration) ---------------
__global__ void __launch_bounds__(256)
zbl_edge_kernel(const float* __restrict__ distances,
                const float* __restrict__ cutoffs,
                const int* __restrict__ senders,
                const int* __restrict__ receivers,
                float* __restrict__ out,
                int n_edges, int n_species) {
    __shared__ float2 stab[MAX_SPECIES];
    for (int t = threadIdx.x; t < n_species; t += blockDim.x)
        stab[t] = g_stab[t];
    float P[8];
#pragma unroll
    for (int k = 0; k < 8; k++) P[k] = g_params[k];
    __syncthreads();

    const unsigned char* spec = reinterpret_cast<const unsigned char*>(g_spec4);

    int i  = blockIdx.x * blockDim.x + threadIdx.x;
    long long e0 = (long long)i * 4;
    if (e0 >= n_edges) return;

    if (e0 + 3 < n_edges) {
        // streaming loads: L2-only, keep L1 for the species gathers
        float4 d4 = __ldcg(reinterpret_cast<const float4*>(distances + e0));
        float4 c4 = __ldcg(reinterpret_cast<const float4*>(cutoffs   + e0));
        int4   s4 = __ldcg(reinterpret_cast<const int4*>(senders    + e0));
        int4   r4 = __ldcg(reinterpret_cast<const int4*>(receivers  + e0));

        // all 8 gathers in flight before compute
        unsigned int sa = __ldg(spec + s4.x), ra = __ldg(spec + r4.x);
        unsigned int sb = __ldg(spec + s4.y), rb = __ldg(spec + r4.y);
        unsigned int sc = __ldg(spec + s4.z), rc = __ldg(spec + r4.z);
        unsigned int sd_ = __ldg(spec + s4.w), rd = __ldg(spec + r4.w);

        float va = zbl_energy(d4.x, c4.x, sa, ra, P, stab);
        float vb = zbl_energy(d4.y, c4.y, sb, rb, P, stab);
        float vc = zbl_energy(d4.z, c4.z, sc, rc, P, stab);
        float vd = zbl_energy(d4.w, c4.w, sd_, rd, P, stab);

        atomicAdd(out + r4.x, va);
        atomicAdd(out + r4.y, vb);
        atomicAdd(out + r4.z, vc);
        atomicAdd(out + r4.w, vd);
    } else {
        for (long long e = e0; e < n_edges; e++) {
            unsigned int si = spec[senders[e]];
            unsigned int ri = spec[receivers[e]];
            float v = zbl_energy(distances[e], cutoffs[e], si, ri, P, stab);
            atomicAdd(out + receivers[e], v);
        }
    }
}

// ---------------------------------------------------------------------------
extern "C" void kernel_launch(void* const* d_in, const int* in_sizes, int n_in,
                              void* d_out, int out_size) {
    const int*   node_species = (const int*)  d_in[0];
    const float* distances    = (const float*)d_in[1];
    const float* cutoffs      = (const float*)d_in[2];
    const int*   senders      = (const int*)  d_in[3];
    const int*   receivers    = (const int*)  d_in[4];
    const int*   index_to_z   = (const int*)  d_in[5];
    const float* a_raw        = (const float*)d_in[6];
    const float* c_raw        = (const float*)d_in[7];
    const float* p_raw        = (const float*)d_in[8];
    const float* d_raw        = (const float*)d_in[9];

    int n_nodes   = in_sizes[0];
    int n_edges   = in_sizes[1];
    int n_species = in_sizes[5];
    float* out    = (float*)d_out;

    {
        int n = (n_nodes > out_size) ? n_nodes : out_size;
        int quads   = (n + 3) / 4;
        int threads = 256;
        int blocks  = (quads + threads - 1) / threads;
        zbl_prep_kernel<<<blocks, threads>>>(a_raw, c_raw, p_raw, d_raw,
                                             index_to_z, node_species, out,
                                             n_species, n_nodes, out_size);
    }

    {
        int threads = 256;
        long long quads = ((long long)n_edges + 3) / 4;
        int blocks  = (int)((quads + threads - 1) / threads);
        zbl_edge_kernel<<<blocks, threads>>>(distances, cutoffs, senders,
                                             receivers, out, n_edges,
                                             n_species);
    }
}